// round 11
// baseline (speedup 1.0000x reference)
#include <cuda_runtime.h>
#include <math.h>

#define NB   2048
#define NDIM 128
#define MLZ  10
#define KAPPA 0.276f
#define TRI  8256      // 128*129/2
#define LPAD 8448      // packed tri, rows padded to multiple of 4 floats

// smem: Lp[8448] | vcur[128] | vprev[128] | yv[128] | tv[128] | U1s[128]
#define SMEM_FLOATS (LPAD + 5 * NDIM)
#define SMEM_BYTES  (SMEM_FLOATS * 4)

__device__ float    g_scr[2 * NB];   // [0..NB) max^2, [NB..2NB) min^2
__device__ unsigned g_ctr = 0;

union F2 { float2 f; unsigned long long u; };

// Single-sync block reduce. SAFETY: consecutive uses of the SAME buf are
// separated by >=1 other __syncthreads() at every call site (redA/redB ping-pong).
__device__ __forceinline__ float blockReduceSum1(float v, float* buf, int tid) {
    #pragma unroll
    for (int o = 16; o > 0; o >>= 1)
        v += __shfl_xor_sync(0xffffffffu, v, o);
    if ((tid & 31) == 0) buf[tid >> 5] = v;
    __syncthreads();
    return (buf[0] + buf[1]) + (buf[2] + buf[3]);
}

// #eigenvalues of the 10x10 symmetric tridiagonal < x (Sturm / LDL recurrence).
__device__ __forceinline__ int sturm_count(const float* a, const float* b2, float x) {
    float q = a[0] - x;
    int c = (q < 0.0f);
    #pragma unroll
    for (int i = 1; i < MLZ; i++) {
        float d = q;
        if (fabsf(d) < 1e-25f) d = (d < 0.0f) ? -1e-25f : 1e-25f;
        q = (a[i] - x) - __fdividef(b2[i - 1], d);
        c += (q < 0.0f);
    }
    return c;
}

__global__ __launch_bounds__(128, 6)
void spectrum_kernel(const float* __restrict__ net_out,
                     const float* __restrict__ U1,
                     const float* __restrict__ vin,
                     float* __restrict__ out) {
    extern __shared__ float sm[];
    float* Lp    = sm;                 // row i (g=i>>2, rm=i&3) at float4 idx (g+1)*(2g+rm)
    float* vcur  = sm + LPAD;
    float* vprev = vcur + NDIM;
    float* yv    = vprev + NDIM;
    float* tv    = yv + NDIM;
    float* U1s   = tv + NDIM;

    __shared__ float redA[4], redB[4];
    __shared__ float alph[MLZ], bet[MLZ], sc[4];
    __shared__ int   amLast;

    const int tid  = threadIdx.x;
    const int b    = blockIdx.x;
    const int lane = tid & 31;
    const int wid  = tid >> 5;
    // SMSP load balancing: rotate each warp's role (column block / row block /
    // vector element block) by batch index so the heavy role (block 0) is
    // spread across SMSPs over the resident CTAs instead of always on SMSP0.
    const int role = (wid + b) & 3;
    const int elem = (role << 5) | lane;   // this thread's vector element / matrix row

    // ---- zero ONLY the row pads (3-rm floats at the end of row tid) ----
    {
        const int i = tid, g2 = i >> 2, rm = i & 3;
        float* rowL = Lp + 4 * (g2 + 1) * (2 * g2 + rm);
        #pragma unroll
        for (int p = 0; p < 3; p++)
            if (rm + 1 + p <= 3) rowL[i + 1 + p] = 0.0f;
    }
    U1s[tid] = U1[(size_t)b * NDIM + tid];
    float v0 = vin[(size_t)b * NDIM + elem];   // coalesced: elem consecutive per warp

    // ---- build padded packed Lp from gmem packed tri (coalesced float4 reads) ----
    {
        const float4* src4 = (const float4*)(net_out + (size_t)b * TRI);
        for (int idx = tid; idx < TRI / 4; idx += 128) {
            float4 v4 = src4[idx];
            int k = idx << 2;
            int i = (int)((__fsqrt_rn(8.0f * (float)k + 1.0f) - 1.0f) * 0.5f);
            while ((i + 1) * (i + 2) / 2 <= k) ++i;
            while (i * (i + 1) / 2 > k) --i;
            int j = k - i * (i + 1) / 2;
            float vals[4] = {v4.x, v4.y, v4.z, v4.w};
            #pragma unroll
            for (int m = 0; m < 4; m++) {
                int gi = i >> 2, ri = i & 3;
                Lp[4 * (gi + 1) * (2 * gi + ri) + j] = vals[m];
                if (++j > i) { ++i; j = 0; }
            }
        }
    }

    // vn = v / ||v||  (this reduce's barrier publishes Lp/U1s too)
    float nrm = sqrtf(blockReduceSum1(v0 * v0, redA, tid));
    vcur[elem]  = v0 / nrm;
    vprev[elem] = 0.0f;

    // ---- dd_opt stencil constants for element `elem` ----
    const int ii = elem >> 4, jj = (elem >> 1) & 7, cc = elem & 1;
    const int xip = (((ii + 1) & 7) << 4) | (jj << 1) | cc;
    const int xim = (((ii - 1) & 7) << 4) | (jj << 1) | cc;
    const int xjp = (ii << 4) | (((jj + 1) & 7) << 1) | cc;
    const int xjm = (ii << 4) | (((jj - 1) & 7) << 1) | cc;
    const float c_u0  = U1s[((ii << 3) + jj) << 1];
    const float c_u1  = U1s[(((ii << 3) + jj) << 1) + 1];
    const float c_u0m = U1s[((((ii - 1) & 7) << 3) + jj) << 1];
    const float c_u1m = U1s[(((ii << 3) + ((jj - 1) & 7)) << 1) + 1];

    // loop-invariant matvec bases (all on `elem`)
    const int g    = elem >> 2;
    const int rb4  = (g + 1) * (2 * g + (elem & 3));  // row matvec: row `elem` base (f4)
    const int mb0  = role << 3;                       // col matvec: warp-uniform first i-group
    const float4* Lr4 = (const float4*)Lp;
    const float4* yv4 = (const float4*)yv;
    const float4* tv4 = (const float4*)tv;

    float beta = 0.0f;
    __syncthreads();   // vcur/vprev visible before hop reads neighbors

    for (int step = 0; step < MLZ; step++) {
        // ---- y = D x (hop stencil), element = elem ----
        {
            float xc  = vcur[elem];
            float hop = c_u0  * vcur[xip] + c_u1  * vcur[xjp]
                      + c_u0m * vcur[xim] + c_u1m * vcur[xjm];
            yv[elem] = xc - KAPPA * hop;
        }
        __syncthreads();                                    // S1

        // ---- t_j = sum_{i>=j} L[i,j] y_i , column j = elem ----
        // warp-synchronized rows i = 4m+k; lane j consecutive -> conflict-free.
        // 4 independent second-order address counters, no serial chain.
        {
            float a0 = 0.f, a1 = 0.f, a2 = 0.f, a3 = 0.f;
            int b0 = (((mb0 + 1) * (2 * mb0    )) << 2) + elem;
            int b1 = (((mb0 + 1) * (2 * mb0 + 1)) << 2) + elem;
            int b2 = (((mb0 + 1) * (2 * mb0 + 2)) << 2) + elem;
            int b3 = (((mb0 + 1) * (2 * mb0 + 3)) << 2) + elem;
            int dinc = (mb0 << 4) + 16;

            // head: 8 i-groups with i < j for some lanes (predicated, not unrolled)
            #pragma unroll 1
            for (int m = mb0; m < mb0 + 8; m++) {
                const int i0 = m << 2;
                float4 y4 = yv4[m];
                float l0 = Lp[b0], l1 = Lp[b1], l2 = Lp[b2], l3 = Lp[b3];
                if (i0     >= elem) a0 += l0 * y4.x;
                if (i0 + 1 >= elem) a1 += l1 * y4.y;
                if (i0 + 2 >= elem) a2 += l2 * y4.z;
                if (i0 + 3 >= elem) a3 += l3 * y4.w;
                b0 += dinc; b1 += dinc + 4; b2 += dinc + 8; b3 += dinc + 12;
                dinc += 16;
            }
            // tail: all rows >= every lane's column (no predicates)
            #pragma unroll 4
            for (int m = mb0 + 8; m < 32; m++) {
                float4 y4 = yv4[m];
                a0 += Lp[b0] * y4.x;
                a1 += Lp[b1] * y4.y;
                a2 += Lp[b2] * y4.z;
                a3 += Lp[b3] * y4.w;
                b0 += dinc; b1 += dinc + 4; b2 += dinc + 8; b3 += dinc + 12;
                dinc += 16;
            }
            tv[elem] = (a0 + a1) + (a2 + a3);
        }
        __syncthreads();                                    // S2

        // ---- w_i = sum_{j<=i} L[i,j] t_j , row i = elem : f4 loads + f32x2 FMA ----
        float wacc;
        {
            F2 accA, accB; accA.u = 0ull; accB.u = 0ull;
            #pragma unroll 4
            for (int q = 0; q <= g; q++) {
                float4 l  = Lr4[rb4 + q];
                float4 t4 = tv4[q];
                F2 la, lb, ta, tb;
                la.f = make_float2(l.x,  l.y);  lb.f = make_float2(l.z,  l.w);
                ta.f = make_float2(t4.x, t4.y); tb.f = make_float2(t4.z, t4.w);
                asm("fma.rn.f32x2 %0, %1, %2, %0;" : "+l"(accA.u) : "l"(la.u), "l"(ta.u));
                asm("fma.rn.f32x2 %0, %1, %2, %0;" : "+l"(accB.u) : "l"(lb.u), "l"(tb.u));
            }
            wacc = (accA.f.x + accB.f.x) + (accA.f.y + accB.f.y);
        }

        // ---- Lanczos recurrence (explicit, matches reference math) ----
        float al = blockReduceSum1(wacc * vcur[elem], redA, tid);    // S3
        float wn = wacc - al * vcur[elem] - beta * vprev[elem];
        float bn = sqrtf(blockReduceSum1(wn * wn, redB, tid));       // S4
        if (tid == 0) { alph[step] = al; bet[step] = bn; }
        vprev[elem] = vcur[elem];
        vcur[elem]  = wn / (bn + 1e-30f);
        beta = bn;
        __syncthreads();                                    // S5
    }

    // ---- eigen tail: warp per target, 32-way multisection (8 iters ~ 40 bits) ----
    {
        float a[MLZ], b2[MLZ - 1];
        #pragma unroll
        for (int i = 0; i < MLZ; i++) a[i] = alph[i];
        #pragma unroll
        for (int i = 0; i < MLZ - 1; i++) { float bb = bet[i]; b2[i] = bb * bb; }

        float lo = 3.0e38f, hi = -3.0e38f;
        #pragma unroll
        for (int i = 0; i < MLZ; i++) {
            float rad = 0.0f;
            if (i > 0)       rad += fabsf(bet[i - 1]);
            if (i < MLZ - 1) rad += fabsf(bet[i]);
            lo = fminf(lo, a[i] - rad);
            hi = fmaxf(hi, a[i] + rad);
        }

        int nneg = sturm_count(a, b2, 0.0f);
        int k;
        if      (wid == 0) k = 0;
        else if (wid == 1) k = MLZ - 1;
        else if (wid == 2) { k = nneg - 1; if (k < 0) k = 0; if (k > MLZ - 1) k = MLZ - 1; }
        else               { k = nneg;     if (k > MLZ - 1) k = MLZ - 1; }

        #pragma unroll 1
        for (int it = 0; it < 8; it++) {
            float wdt = (hi - lo) * (1.0f / 33.0f);
            float x   = lo + wdt * (float)(lane + 1);
            int   c   = sturm_count(a, b2, x);
            unsigned m = __ballot_sync(0xffffffffu, c > k);
            int idx = (m == 0u) ? 32 : (__ffs(m) - 1);
            float nlo = lo + wdt * (float)idx;
            float nhi = (idx == 32) ? hi : lo + wdt * (float)(idx + 1);
            lo = nlo; hi = nhi;
        }
        if (lane == 0) sc[wid] = fabsf(0.5f * (lo + hi));
    }
    __syncthreads();

    if (tid == 0) {
        float mx = fmaxf(sc[0], sc[1]);   // max |lambda|
        float mn = fminf(sc[2], sc[3]);   // min |lambda|
        g_scr[b]      = mx * mx;
        g_scr[NB + b] = mn * mn;
        __threadfence();
        unsigned t = atomicAdd(&g_ctr, 1u);
        amLast = (t == NB - 1);
    }
    __syncthreads();

    // ---- last CTA reduces all batches (fixed order => deterministic) ----
    if (amLast) {
        __threadfence();
        const volatile float* scr = g_scr;
        float s1 = 0.0f, s2 = 0.0f;
        for (int i = tid; i < NB; i += 128) { s1 += scr[i]; s2 += scr[NB + i]; }
        float S1 = blockReduceSum1(s1, redA, tid);
        float S2 = blockReduceSum1(s2, redB, tid);
        if (tid == 0) {
            out[0] = (S1 - S2) * (1.0f / (float)NB);
            g_ctr = 0;   // reset for next graph replay
        }
    }
}

extern "C" void kernel_launch(void* const* d_in, const int* in_sizes, int n_in,
                              void* d_out, int out_size) {
    const float* net_out = (const float*)d_in[0];
    const float* U1      = (const float*)d_in[1];
    const float* v       = (const float*)d_in[2];
    (void)in_sizes; (void)n_in; (void)out_size;

    spectrum_kernel<<<NB, 128, SMEM_BYTES>>>(net_out, U1, v, (float*)d_out);
}

// round 12
// speedup vs baseline: 1.6443x; 1.6443x over previous
#include <cuda_runtime.h>
#include <math.h>

#define NB   2048
#define NDIM 128
#define MLZ  10
#define KAPPA 0.276f
#define TRI  8256      // 128*129/2
#define LPAD 8448      // packed tri, rows padded to multiple of 4 floats

// smem: Lp[8448] | wv[128] (wn exchange) | yv[128] | tv[128] | U1s[128]
#define SMEM_FLOATS (LPAD + 4 * NDIM)
#define SMEM_BYTES  (SMEM_FLOATS * 4)

__device__ float    g_scr[2 * NB];   // [0..NB) max^2, [NB..2NB) min^2
__device__ unsigned g_ctr = 0;

union F2 { float2 f; unsigned long long u; };

// Single-sync block reduce. SAFETY: consecutive uses of the SAME buf are
// separated by >=1 other __syncthreads() at every call site (redA/redB ping-pong).
__device__ __forceinline__ float blockReduceSum1(float v, float* buf, int tid) {
    #pragma unroll
    for (int o = 16; o > 0; o >>= 1)
        v += __shfl_xor_sync(0xffffffffu, v, o);
    if ((tid & 31) == 0) buf[tid >> 5] = v;
    __syncthreads();
    return (buf[0] + buf[1]) + (buf[2] + buf[3]);
}

// #eigenvalues of the 10x10 symmetric tridiagonal < x (Sturm / LDL recurrence).
__device__ __forceinline__ int sturm_count(const float* a, const float* b2, float x) {
    float q = a[0] - x;
    int c = (q < 0.0f);
    #pragma unroll
    for (int i = 1; i < MLZ; i++) {
        float d = q;
        if (fabsf(d) < 1e-25f) d = (d < 0.0f) ? -1e-25f : 1e-25f;
        q = (a[i] - x) - __fdividef(b2[i - 1], d);
        c += (q < 0.0f);
    }
    return c;
}

__global__ __launch_bounds__(128, 6)
void spectrum_kernel(const float* __restrict__ net_out,
                     const float* __restrict__ U1,
                     const float* __restrict__ vin,
                     float* __restrict__ out) {
    extern __shared__ float sm[];
    float* Lp  = sm;                 // row i (g=i>>2, rm=i&3) at float4 idx (g+1)*(2g+rm)
    float* wv  = sm + LPAD;          // unnormalized Lanczos vector (neighbor exchange)
    float* yv  = wv + NDIM;
    float* tv  = yv + NDIM;
    float* U1s = tv + NDIM;

    __shared__ float redA[4], redB[4];
    __shared__ float alph[MLZ], bet[MLZ], sc[4];
    __shared__ int   amLast;

    const int tid = threadIdx.x;
    const int b   = blockIdx.x;

    // ---- zero ONLY the row pads (3-rm floats at the end of row tid) ----
    {
        const int i = tid, g2 = i >> 2, rm = i & 3;
        float* rowL = Lp + 4 * (g2 + 1) * (2 * g2 + rm);
        #pragma unroll
        for (int p = 0; p < 3; p++)
            if (rm + 1 + p <= 3) rowL[i + 1 + p] = 0.0f;
    }
    U1s[tid] = U1[(size_t)b * NDIM + tid];
    float v0 = vin[(size_t)b * NDIM + tid];
    wv[tid] = v0;                      // unnormalized v; published by norm-reduce barrier

    // ---- build padded packed Lp from gmem packed tri (coalesced float4 reads) ----
    {
        const float4* src4 = (const float4*)(net_out + (size_t)b * TRI);
        for (int idx = tid; idx < TRI / 4; idx += 128) {
            float4 v4 = src4[idx];
            int k = idx << 2;
            int i = (int)((__fsqrt_rn(8.0f * (float)k + 1.0f) - 1.0f) * 0.5f);
            while ((i + 1) * (i + 2) / 2 <= k) ++i;
            while (i * (i + 1) / 2 > k) --i;
            int j = k - i * (i + 1) / 2;
            float vals[4] = {v4.x, v4.y, v4.z, v4.w};
            #pragma unroll
            for (int m = 0; m < 4; m++) {
                int gi = i >> 2, ri = i & 3;
                Lp[4 * (gi + 1) * (2 * gi + ri) + j] = vals[m];
                if (++j > i) { ++i; j = 0; }
            }
        }
    }

    // ||v||  (this reduce's barrier publishes Lp/U1s/wv too)
    float nrm  = sqrtf(blockReduceSum1(v0 * v0, redA, tid));
    float rinv = 1.0f / nrm;           // scale carried in registers
    float vc   = v0 * rinv;            // own vcur element (register)
    float vp   = 0.0f;                 // own vprev element (register)
    float wn_own = v0;                 // own unnormalized vector element

    // ---- dd_opt stencil constants (kappa folded in) ----
    const int ii = tid >> 4, jj = (tid >> 1) & 7, cc = tid & 1;
    const int xip = (((ii + 1) & 7) << 4) | (jj << 1) | cc;
    const int xim = (((ii - 1) & 7) << 4) | (jj << 1) | cc;
    const int xjp = (ii << 4) | (((jj + 1) & 7) << 1) | cc;
    const int xjm = (ii << 4) | (((jj - 1) & 7) << 1) | cc;
    const float k0 = KAPPA * U1s[((ii << 3) + jj) << 1];
    const float k1 = KAPPA * U1s[(((ii << 3) + jj) << 1) + 1];
    const float k2 = KAPPA * U1s[((((ii - 1) & 7) << 3) + jj) << 1];
    const float k3 = KAPPA * U1s[(((ii << 3) + ((jj - 1) & 7)) << 1) + 1];

    // loop-invariant matvec bases
    const int g    = tid >> 2;
    const int rb4  = (g + 1) * (2 * g + (tid & 3));   // row matvec: this thread's row base (f4)
    const int mb0  = (tid & ~31) >> 2;                // col matvec: warp-uniform first i-group
    const float4* Lr4 = (const float4*)Lp;
    const float4* yv4 = (const float4*)yv;
    const float4* tv4 = (const float4*)tv;

    float beta = 0.0f;

    for (int step = 0; step < MLZ; step++) {
        // ---- y = D x (hop stencil on unnormalized wv, scaled by rinv) ----
        // y = vc - kappa*hop(vcur) = (wn_own - hop_k(wn)) * rinv   (hop linear)
        {
            float hopv = k0 * wv[xip] + k1 * wv[xjp]
                       + k2 * wv[xim] + k3 * wv[xjm];
            yv[tid] = (wn_own - hopv) * rinv;
        }
        __syncthreads();                                    // S1

        // ---- t_j = sum_{i>=j} L[i,j] y_i ----
        // warp-synchronized rows i = 4m+k; lane j = tid -> consecutive floats (conflict-free).
        // 4 independent second-order address counters, no serial chain through the loads.
        {
            float a0 = 0.f, a1 = 0.f, a2 = 0.f, a3 = 0.f;
            int b0 = (((mb0 + 1) * (2 * mb0    )) << 2) + tid;
            int b1 = (((mb0 + 1) * (2 * mb0 + 1)) << 2) + tid;
            int b2 = (((mb0 + 1) * (2 * mb0 + 2)) << 2) + tid;
            int b3 = (((mb0 + 1) * (2 * mb0 + 3)) << 2) + tid;
            int dinc = (mb0 << 4) + 16;

            // head: 8 i-groups with i < j for some lanes (predicated, not unrolled)
            #pragma unroll 1
            for (int m = mb0; m < mb0 + 8; m++) {
                const int i0 = m << 2;
                float4 y4 = yv4[m];
                float l0 = Lp[b0], l1 = Lp[b1], l2 = Lp[b2], l3 = Lp[b3];
                if (i0     >= tid) a0 += l0 * y4.x;
                if (i0 + 1 >= tid) a1 += l1 * y4.y;
                if (i0 + 2 >= tid) a2 += l2 * y4.z;
                if (i0 + 3 >= tid) a3 += l3 * y4.w;
                b0 += dinc; b1 += dinc + 4; b2 += dinc + 8; b3 += dinc + 12;
                dinc += 16;
            }
            // tail: all rows >= every lane's column (no predicates)
            #pragma unroll 4
            for (int m = mb0 + 8; m < 32; m++) {
                float4 y4 = yv4[m];
                a0 += Lp[b0] * y4.x;
                a1 += Lp[b1] * y4.y;
                a2 += Lp[b2] * y4.z;
                a3 += Lp[b3] * y4.w;
                b0 += dinc; b1 += dinc + 4; b2 += dinc + 8; b3 += dinc + 12;
                dinc += 16;
            }
            tv[tid] = (a0 + a1) + (a2 + a3);
        }
        __syncthreads();                                    // S2

        // ---- w_i = sum_{j<=i} L[i,j] t_j : float4 loads + packed f32x2 FMA ----
        float wacc;
        {
            F2 accA, accB; accA.u = 0ull; accB.u = 0ull;
            #pragma unroll 4
            for (int q = 0; q <= g; q++) {
                float4 l  = Lr4[rb4 + q];
                float4 t4 = tv4[q];
                F2 la, lb, ta, tb;
                la.f = make_float2(l.x,  l.y);  lb.f = make_float2(l.z,  l.w);
                ta.f = make_float2(t4.x, t4.y); tb.f = make_float2(t4.z, t4.w);
                asm("fma.rn.f32x2 %0, %1, %2, %0;" : "+l"(accA.u) : "l"(la.u), "l"(ta.u));
                asm("fma.rn.f32x2 %0, %1, %2, %0;" : "+l"(accB.u) : "l"(lb.u), "l"(tb.u));
            }
            wacc = (accA.f.x + accB.f.x) + (accA.f.y + accB.f.y);
        }

        // ---- Lanczos recurrence; vc/vp in registers, wn exchanged via wv ----
        float al = blockReduceSum1(wacc * vc, redA, tid);            // S3
        float wn = wacc - al * vc - beta * vp;
        wv[tid] = wn;                    // published by the S4 barrier below
        float bn = sqrtf(blockReduceSum1(wn * wn, redB, tid));       // S4
        if (tid == 0) { alph[step] = al; bet[step] = bn; }
        rinv = 1.0f / (bn + 1e-30f);
        vp = vc;
        vc = wn * rinv;
        wn_own = wn;
        beta = bn;
        // no S5: next hop reads wv, already published by S4
    }

    // ---- eigen tail: warp per target, 32-way multisection (8 iters ~ 40 bits) ----
    {
        const int wid  = tid >> 5;
        const int lane = tid & 31;

        float a[MLZ], b2[MLZ - 1];
        #pragma unroll
        for (int i = 0; i < MLZ; i++) a[i] = alph[i];
        #pragma unroll
        for (int i = 0; i < MLZ - 1; i++) { float bb = bet[i]; b2[i] = bb * bb; }

        float lo = 3.0e38f, hi = -3.0e38f;
        #pragma unroll
        for (int i = 0; i < MLZ; i++) {
            float rad = 0.0f;
            if (i > 0)       rad += fabsf(bet[i - 1]);
            if (i < MLZ - 1) rad += fabsf(bet[i]);
            lo = fminf(lo, a[i] - rad);
            hi = fmaxf(hi, a[i] + rad);
        }

        int nneg = sturm_count(a, b2, 0.0f);
        int k;
        if      (wid == 0) k = 0;
        else if (wid == 1) k = MLZ - 1;
        else if (wid == 2) { k = nneg - 1; if (k < 0) k = 0; if (k > MLZ - 1) k = MLZ - 1; }
        else               { k = nneg;     if (k > MLZ - 1) k = MLZ - 1; }

        #pragma unroll 1
        for (int it = 0; it < 8; it++) {
            float wdt = (hi - lo) * (1.0f / 33.0f);
            float x   = lo + wdt * (float)(lane + 1);
            int   c   = sturm_count(a, b2, x);
            unsigned m = __ballot_sync(0xffffffffu, c > k);
            int idx = (m == 0u) ? 32 : (__ffs(m) - 1);
            float nlo = lo + wdt * (float)idx;
            float nhi = (idx == 32) ? hi : lo + wdt * (float)(idx + 1);
            lo = nlo; hi = nhi;
        }
        if (lane == 0) sc[wid] = fabsf(0.5f * (lo + hi));
    }
    __syncthreads();

    if (tid == 0) {
        float mx = fmaxf(sc[0], sc[1]);   // max |lambda|
        float mn = fminf(sc[2], sc[3]);   // min |lambda|
        g_scr[b]      = mx * mx;
        g_scr[NB + b] = mn * mn;
        __threadfence();
        unsigned t = atomicAdd(&g_ctr, 1u);
        amLast = (t == NB - 1);
    }
    __syncthreads();

    // ---- last CTA reduces all batches (fixed order => deterministic) ----
    if (amLast) {
        __threadfence();
        const volatile float* scr = g_scr;
        float s1 = 0.0f, s2 = 0.0f;
        for (int i = tid; i < NB; i += 128) { s1 += scr[i]; s2 += scr[NB + i]; }
        float S1 = blockReduceSum1(s1, redA, tid);
        float S2 = blockReduceSum1(s2, redB, tid);
        if (tid == 0) {
            out[0] = (S1 - S2) * (1.0f / (float)NB);
            g_ctr = 0;   // reset for next graph replay
        }
    }
}

extern "C" void kernel_launch(void* const* d_in, const int* in_sizes, int n_in,
                              void* d_out, int out_size) {
    const float* net_out = (const float*)d_in[0];
    const float* U1      = (const float*)d_in[1];
    const float* v       = (const float*)d_in[2];
    (void)in_sizes; (void)n_in; (void)out_size;

    spectrum_kernel<<<NB, 128, SMEM_BYTES>>>(net_out, U1, v, (float*)d_out);
}

// round 13
// speedup vs baseline: 1.6898x; 1.0277x over previous
#include <cuda_runtime.h>
#include <math.h>

#define NB   2048
#define NDIM 128
#define MLZ  10
#define KAPPA 0.276f
#define TRI  8256      // 128*129/2
#define LPAD 8448      // packed tri, rows padded to multiple of 4 floats

// smem: Lp[8448] | vcur[128] | vprev[128] | yv[128] | tv[128] | U1s[128]
#define SMEM_FLOATS (LPAD + 5 * NDIM)
#define SMEM_BYTES  (SMEM_FLOATS * 4)

__device__ float    g_scr[2 * NB];   // [0..NB) max^2, [NB..2NB) min^2
__device__ unsigned g_ctr = 0;

// Compile-time map: packed-tri index k -> padded-layout float offset.
// Row i (g=i>>2, rm=i&3) starts at float offset 4*(g+1)*(2g+rm); element j adds j.
// Max offset 8447 < 65536 -> uint16.
struct alignas(16) OffTab {
    unsigned short v[TRI];
    constexpr OffTab() : v() {
        int i = 0, j = 0;
        for (int k = 0; k < TRI; k++) {
            int gi = i >> 2, ri = i & 3;
            v[k] = (unsigned short)(4 * (gi + 1) * (2 * gi + ri) + j);
            if (++j > i) { ++i; j = 0; }
        }
    }
};
__device__ static const OffTab g_off = OffTab();

union F2 { float2 f; unsigned long long u; };

// Single-sync block reduce. SAFETY: consecutive uses of the SAME buf are
// separated by >=1 other __syncthreads() at every call site (redA/redB ping-pong).
__device__ __forceinline__ float blockReduceSum1(float v, float* buf, int tid) {
    #pragma unroll
    for (int o = 16; o > 0; o >>= 1)
        v += __shfl_xor_sync(0xffffffffu, v, o);
    if ((tid & 31) == 0) buf[tid >> 5] = v;
    __syncthreads();
    return (buf[0] + buf[1]) + (buf[2] + buf[3]);
}

// #eigenvalues of the 10x10 symmetric tridiagonal < x (Sturm / LDL recurrence).
__device__ __forceinline__ int sturm_count(const float* a, const float* b2, float x) {
    float q = a[0] - x;
    int c = (q < 0.0f);
    #pragma unroll
    for (int i = 1; i < MLZ; i++) {
        float d = q;
        if (fabsf(d) < 1e-25f) d = (d < 0.0f) ? -1e-25f : 1e-25f;
        q = (a[i] - x) - __fdividef(b2[i - 1], d);
        c += (q < 0.0f);
    }
    return c;
}

__global__ __launch_bounds__(128, 6)
void spectrum_kernel(const float* __restrict__ net_out,
                     const float* __restrict__ U1,
                     const float* __restrict__ vin,
                     float* __restrict__ out) {
    extern __shared__ float sm[];
    float* Lp    = sm;                 // row i (g=i>>2, rm=i&3) at float4 idx (g+1)*(2g+rm)
    float* vcur  = sm + LPAD;
    float* vprev = vcur + NDIM;
    float* yv    = vprev + NDIM;
    float* tv    = yv + NDIM;
    float* U1s   = tv + NDIM;

    __shared__ float redA[4], redB[4];
    __shared__ float alph[MLZ], bet[MLZ], sc[4];
    __shared__ int   amLast;

    const int tid = threadIdx.x;
    const int b   = blockIdx.x;

    // ---- zero ONLY the row pads (3-rm floats at the end of row tid) ----
    {
        const int i = tid, g2 = i >> 2, rm = i & 3;
        float* rowL = Lp + 4 * (g2 + 1) * (2 * g2 + rm);
        #pragma unroll
        for (int p = 0; p < 3; p++)
            if (rm + 1 + p <= 3) rowL[i + 1 + p] = 0.0f;
    }
    U1s[tid] = U1[(size_t)b * NDIM + tid];
    float v0 = vin[(size_t)b * NDIM + tid];

    // ---- build padded packed Lp via precomputed offset table ----
    {
        const float4*  src4 = (const float4*)(net_out + (size_t)b * TRI);
        const ushort4* off4 = (const ushort4*)g_off.v;
        #pragma unroll 4
        for (int idx = tid; idx < TRI / 4; idx += 128) {
            float4  v4 = src4[idx];
            ushort4 o  = off4[idx];
            Lp[o.x] = v4.x;
            Lp[o.y] = v4.y;
            Lp[o.z] = v4.z;
            Lp[o.w] = v4.w;
        }
    }

    // vn = v / ||v||  (this reduce's barrier publishes Lp/U1s too)
    float nrm = sqrtf(blockReduceSum1(v0 * v0, redA, tid));
    vcur[tid]  = v0 / nrm;
    vprev[tid] = 0.0f;

    // ---- dd_opt stencil constants ----
    const int ii = tid >> 4, jj = (tid >> 1) & 7, cc = tid & 1;
    const int xip = (((ii + 1) & 7) << 4) | (jj << 1) | cc;
    const int xim = (((ii - 1) & 7) << 4) | (jj << 1) | cc;
    const int xjp = (ii << 4) | (((jj + 1) & 7) << 1) | cc;
    const int xjm = (ii << 4) | (((jj - 1) & 7) << 1) | cc;
    const float c_u0  = U1s[((ii << 3) + jj) << 1];
    const float c_u1  = U1s[(((ii << 3) + jj) << 1) + 1];
    const float c_u0m = U1s[((((ii - 1) & 7) << 3) + jj) << 1];
    const float c_u1m = U1s[(((ii << 3) + ((jj - 1) & 7)) << 1) + 1];

    // loop-invariant matvec bases
    const int g    = tid >> 2;
    const int rb4  = (g + 1) * (2 * g + (tid & 3));   // row matvec: this thread's row base (f4)
    const int mb0  = (tid & ~31) >> 2;                // col matvec: warp-uniform first i-group
    const float4* Lr4 = (const float4*)Lp;
    const float4* yv4 = (const float4*)yv;
    const float4* tv4 = (const float4*)tv;

    float beta = 0.0f;
    __syncthreads();   // vcur/vprev visible before hop reads neighbors

    for (int step = 0; step < MLZ; step++) {
        // ---- y = D x (hop stencil) ----
        {
            float xc  = vcur[tid];
            float hop = c_u0  * vcur[xip] + c_u1  * vcur[xjp]
                      + c_u0m * vcur[xim] + c_u1m * vcur[xjm];
            yv[tid] = xc - KAPPA * hop;
        }
        __syncthreads();                                    // S1

        // ---- t_j = sum_{i>=j} L[i,j] y_i ----
        // warp-synchronized rows i = 4m+k; lane j = tid -> consecutive floats (conflict-free).
        // 4 independent second-order address counters, no serial chain through the loads.
        {
            float a0 = 0.f, a1 = 0.f, a2 = 0.f, a3 = 0.f;
            int b0 = (((mb0 + 1) * (2 * mb0    )) << 2) + tid;
            int b1 = (((mb0 + 1) * (2 * mb0 + 1)) << 2) + tid;
            int b2 = (((mb0 + 1) * (2 * mb0 + 2)) << 2) + tid;
            int b3 = (((mb0 + 1) * (2 * mb0 + 3)) << 2) + tid;
            int dinc = (mb0 << 4) + 16;

            // head: 8 i-groups with i < j for some lanes (predicated, not unrolled)
            #pragma unroll 1
            for (int m = mb0; m < mb0 + 8; m++) {
                const int i0 = m << 2;
                float4 y4 = yv4[m];
                float l0 = Lp[b0], l1 = Lp[b1], l2 = Lp[b2], l3 = Lp[b3];
                if (i0     >= tid) a0 += l0 * y4.x;
                if (i0 + 1 >= tid) a1 += l1 * y4.y;
                if (i0 + 2 >= tid) a2 += l2 * y4.z;
                if (i0 + 3 >= tid) a3 += l3 * y4.w;
                b0 += dinc; b1 += dinc + 4; b2 += dinc + 8; b3 += dinc + 12;
                dinc += 16;
            }
            // tail: all rows >= every lane's column (no predicates)
            #pragma unroll 4
            for (int m = mb0 + 8; m < 32; m++) {
                float4 y4 = yv4[m];
                a0 += Lp[b0] * y4.x;
                a1 += Lp[b1] * y4.y;
                a2 += Lp[b2] * y4.z;
                a3 += Lp[b3] * y4.w;
                b0 += dinc; b1 += dinc + 4; b2 += dinc + 8; b3 += dinc + 12;
                dinc += 16;
            }
            tv[tid] = (a0 + a1) + (a2 + a3);
        }
        __syncthreads();                                    // S2

        // ---- w_i = sum_{j<=i} L[i,j] t_j : float4 loads + packed f32x2 FMA ----
        float wacc;
        {
            F2 accA, accB; accA.u = 0ull; accB.u = 0ull;
            #pragma unroll 4
            for (int q = 0; q <= g; q++) {
                float4 l  = Lr4[rb4 + q];
                float4 t4 = tv4[q];
                F2 la, lb, ta, tb;
                la.f = make_float2(l.x,  l.y);  lb.f = make_float2(l.z,  l.w);
                ta.f = make_float2(t4.x, t4.y); tb.f = make_float2(t4.z, t4.w);
                asm("fma.rn.f32x2 %0, %1, %2, %0;" : "+l"(accA.u) : "l"(la.u), "l"(ta.u));
                asm("fma.rn.f32x2 %0, %1, %2, %0;" : "+l"(accB.u) : "l"(lb.u), "l"(tb.u));
            }
            wacc = (accA.f.x + accB.f.x) + (accA.f.y + accB.f.y);
        }

        // ---- Lanczos recurrence (explicit, matches reference math) ----
        float al = blockReduceSum1(wacc * vcur[tid], redA, tid);     // S3
        float wn = wacc - al * vcur[tid] - beta * vprev[tid];
        float bn = sqrtf(blockReduceSum1(wn * wn, redB, tid));       // S4
        if (tid == 0) { alph[step] = al; bet[step] = bn; }
        vprev[tid] = vcur[tid];
        vcur[tid]  = wn / (bn + 1e-30f);
        beta = bn;
        __syncthreads();                                    // S5
    }

    // ---- eigen tail: warp per target, 32-way multisection (8 iters ~ 40 bits) ----
    {
        const int wid  = tid >> 5;
        const int lane = tid & 31;

        float a[MLZ], b2[MLZ - 1];
        #pragma unroll
        for (int i = 0; i < MLZ; i++) a[i] = alph[i];
        #pragma unroll
        for (int i = 0; i < MLZ - 1; i++) { float bb = bet[i]; b2[i] = bb * bb; }

        float lo = 3.0e38f, hi = -3.0e38f;
        #pragma unroll
        for (int i = 0; i < MLZ; i++) {
            float rad = 0.0f;
            if (i > 0)       rad += fabsf(bet[i - 1]);
            if (i < MLZ - 1) rad += fabsf(bet[i]);
            lo = fminf(lo, a[i] - rad);
            hi = fmaxf(hi, a[i] + rad);
        }

        int nneg = sturm_count(a, b2, 0.0f);
        int k;
        if      (wid == 0) k = 0;
        else if (wid == 1) k = MLZ - 1;
        else if (wid == 2) { k = nneg - 1; if (k < 0) k = 0; if (k > MLZ - 1) k = MLZ - 1; }
        else               { k = nneg;     if (k > MLZ - 1) k = MLZ - 1; }

        #pragma unroll 1
        for (int it = 0; it < 8; it++) {
            float wdt = (hi - lo) * (1.0f / 33.0f);
            float x   = lo + wdt * (float)(lane + 1);
            int   c   = sturm_count(a, b2, x);
            unsigned m = __ballot_sync(0xffffffffu, c > k);
            int idx = (m == 0u) ? 32 : (__ffs(m) - 1);
            float nlo = lo + wdt * (float)idx;
            float nhi = (idx == 32) ? hi : lo + wdt * (float)(idx + 1);
            lo = nlo; hi = nhi;
        }
        if (lane == 0) sc[wid] = fabsf(0.5f * (lo + hi));
    }
    __syncthreads();

    if (tid == 0) {
        float mx = fmaxf(sc[0], sc[1]);   // max |lambda|
        float mn = fminf(sc[2], sc[3]);   // min |lambda|
        g_scr[b]      = mx * mx;
        g_scr[NB + b] = mn * mn;
        __threadfence();
        unsigned t = atomicAdd(&g_ctr, 1u);
        amLast = (t == NB - 1);
    }
    __syncthreads();

    // ---- last CTA reduces all batches (fixed order => deterministic) ----
    if (amLast) {
        __threadfence();
        const volatile float* scr = g_scr;
        float s1 = 0.0f, s2 = 0.0f;
        for (int i = tid; i < NB; i += 128) { s1 += scr[i]; s2 += scr[NB + i]; }
        float S1 = blockReduceSum1(s1, redA, tid);
        float S2 = blockReduceSum1(s2, redB, tid);
        if (tid == 0) {
            out[0] = (S1 - S2) * (1.0f / (float)NB);
            g_ctr = 0;   // reset for next graph replay
        }
    }
}

extern "C" void kernel_launch(void* const* d_in, const int* in_sizes, int n_in,
                              void* d_out, int out_size) {
    const float* net_out = (const float*)d_in[0];
    const float* U1      = (const float*)d_in[1];
    const float* v       = (const float*)d_in[2];
    (void)in_sizes; (void)n_in; (void)out_size;

    spectrum_kernel<<<NB, 128, SMEM_BYTES>>>(net_out, U1, v, (float*)d_out);
}